// round 7
// baseline (speedup 1.0000x reference)
#include <cuda_runtime.h>
#include <stdint.h>

// MSE of (1 - output[i, target[i]])^2 over N rows.
// output: [N,2] fp32, target: [N] int32 in {0,1} (JAX x64 disabled -> int32).
// Pure HBM-bound streaming reduction: 201 MB in -> 1 float out.

#define THREADS 256
#define BLOCKS  4736   // 148 SMs * 32

__global__ void zero_out_kernel(float* out) {
    out[0] = 0.0f;
}

__global__ __launch_bounds__(THREADS) void floss_kernel(
    const float4* __restrict__ out4,   // output reinterpreted: 2 rows per float4
    const int4*  __restrict__ tgt4,    // 4 targets per int4
    float* __restrict__ out,
    int n_quads,       // N/4
    float inv_n)
{
    int tid = blockIdx.x * THREADS + threadIdx.x;
    int stride = BLOCKS * THREADS;

    float acc = 0.0f;

    // Each iteration: 4 rows = two float4 (output) + one int4 (targets), 48B coalesced.
    #pragma unroll 4
    for (int i = tid; i < n_quads; i += stride) {
        float4 a = out4[2 * i];       // rows 4i, 4i+1
        float4 b = out4[2 * i + 1];   // rows 4i+2, 4i+3
        int4 t = tgt4[i];
        float x0 = (t.x != 0) ? a.y : a.x;
        float x1 = (t.y != 0) ? a.w : a.z;
        float x2 = (t.z != 0) ? b.y : b.x;
        float x3 = (t.w != 0) ? b.w : b.z;
        float d0 = 1.0f - x0;
        float d1 = 1.0f - x1;
        float d2 = 1.0f - x2;
        float d3 = 1.0f - x3;
        acc = fmaf(d0, d0, acc);
        acc = fmaf(d1, d1, acc);
        acc = fmaf(d2, d2, acc);
        acc = fmaf(d3, d3, acc);
    }

    // warp reduce
    #pragma unroll
    for (int m = 16; m > 0; m >>= 1)
        acc += __shfl_xor_sync(0xFFFFFFFFu, acc, m);

    // block reduce
    __shared__ float warp_sums[THREADS / 32];
    int lane = threadIdx.x & 31;
    int wid = threadIdx.x >> 5;
    if (lane == 0) warp_sums[wid] = acc;
    __syncthreads();

    if (wid == 0) {
        acc = (lane < THREADS / 32) ? warp_sums[lane] : 0.0f;
        #pragma unroll
        for (int m = 4; m > 0; m >>= 1)
            acc += __shfl_xor_sync(0xFFFFFFFFu, acc, m);
        if (lane == 0)
            atomicAdd(out, acc * inv_n);
    }
}

extern "C" void kernel_launch(void* const* d_in, const int* in_sizes, int n_in,
                              void* d_out, int out_size) {
    const float4* output = (const float4*)d_in[0];  // [N,2] fp32
    const int4*   target = (const int4*)d_in[1];    // [N] int32
    float* out = (float*)d_out;

    int n = in_sizes[1];          // N = element count of target
    int n_quads = n >> 2;         // N = 2^24, divisible by 4
    float inv_n = 1.0f / (float)n;

    zero_out_kernel<<<1, 1>>>(out);
    floss_kernel<<<BLOCKS, THREADS>>>(output, target, out, n_quads, inv_n);
}